// round 15
// baseline (speedup 1.0000x reference)
#include <cuda_runtime.h>
#include <cuda_fp16.h>
#include <math.h>
#include <stdint.h>

// Problem constants
#define Bx  16
#define Sx  1024
#define Hx  1024
#define Ox  256
#define Lx  4
#define NHx 8
#define DHx 128
#define Mx  (Bx*Sx)   // 16384 rows
#define CT  32        // scan chunk length
#define CC  (Sx/CT)   // 32 chunks
#define JG  8         // wsum j-split

typedef unsigned long long u64;

// ---------------- scratch (device globals: no allocation allowed) ----------
__device__ float g_bufA[(size_t)Mx * Hx];   // last-layer fp32 activations
__device__ float g_bufF[(size_t)Mx * Hx];   // f16 gate-f preact (as half)
__device__ float g_bufI[(size_t)Mx * Hx];   // f16 gate-i preact (as half)
__device__ float g_bufH[(size_t)Mx * Hx];   // f16 h~ preact (as half)
__device__ float g_chP[Bx * Hx * CC];
__device__ float g_chQ[Bx * Hx * CC];
__device__ float g_scores[Bx * NHx * Sx];
__device__ float g_q[Bx * Hx];
__device__ float g_u[Bx * NHx * Hx];
__device__ float g_wp[JG * Bx * NHx * Hx];
__device__ float g_w[Bx * NHx * Hx];
__device__ float g_o[Bx * Hx];
__device__ float g_last[Bx * Hx];

// fp16 buffers
#define NWF 4194304
#define NWTOT (3*NWF)
__device__ __half g_WH[NWTOT];
__device__ __half g_AH[(size_t)Mx * Hx];

// ======================= helpers ===========================================
__device__ __forceinline__ uint32_t smem_u32(const void* p) {
    uint32_t a;
    asm("{ .reg .u64 t; cvta.to.shared.u64 t, %1; cvt.u32.u64 %0, t; }"
        : "=r"(a) : "l"(p));
    return a;
}
__device__ __forceinline__ void cpa16(uint32_t dst, const void* src) {
    asm volatile("cp.async.cg.shared.global [%0], [%1], 16;" :: "r"(dst), "l"(src));
}
__device__ __forceinline__ void ldm4(uint32_t& r0, uint32_t& r1,
                                     uint32_t& r2, uint32_t& r3, uint32_t a) {
    asm volatile("ldmatrix.sync.aligned.m8n8.x4.shared.b16 {%0,%1,%2,%3}, [%4];"
        : "=r"(r0), "=r"(r1), "=r"(r2), "=r"(r3) : "r"(a));
}
__device__ __forceinline__ void mma16816(float* d, const uint32_t* a, const uint32_t* b) {
    asm volatile("mma.sync.aligned.m16n8k16.row.col.f32.f16.f16.f32 "
        "{%0,%1,%2,%3}, {%4,%5,%6,%7}, {%8,%9}, {%0,%1,%2,%3};"
        : "+f"(d[0]), "+f"(d[1]), "+f"(d[2]), "+f"(d[3])
        : "r"(a[0]), "r"(a[1]), "r"(a[2]), "r"(a[3]), "r"(b[0]), "r"(b[1]));
}
__device__ __forceinline__ float fast_rcp(float x) {
    float r; asm("rcp.approx.f32 %0, %1;" : "=f"(r) : "f"(x)); return r;
}

// ======================= fused multi-output pure-fp16 HGEMM ================
// CTA tile 128x128, 256 threads, K-chunk 64 (two 32-sub-tiles per stage),
// 3-stage cp.async, 96 KB smem (2 CTAs/SM). All outputs f16.
struct GemmArgs {
    const __half* WH[3];
    const float*  bias[3];
    __half*       C[3];
};

#define SUB_SZ 8192
#define STG_SZ 32768          // A: 2x8K, B: 2x8K
#define T_A 0
#define T_B 16384
#define NSTG 3
#define SMEMB (NSTG * STG_SZ) // 96 KB

__global__ __launch_bounds__(256) void hgemm_fused_k(
    const __half* __restrict__ AH, GemmArgs ga)
{
    extern __shared__ __align__(1024) char smem[];
    const uint32_t sb = smem_u32(smem);
    const int tid = threadIdx.x;
    const int wid = tid >> 5, lane = tid & 31;
    const int region = blockIdx.x >> 3;
    const int bx = blockIdx.x & 7;
    const int by = blockIdx.y;

    const __half* WH = ga.WH[region];
    const float*  bias = ga.bias[region];
    __half*       Ch = ga.C[region];

    const int lm  = tid >> 1;
    const int lc0 = (tid & 1) * 2;
    const size_t aoff = (size_t)(by * 128 + lm) * Hx;
    const size_t boff = (size_t)(bx * 128 + lm) * Hx;
    const int sws = (lm >> 1) & 3;
    const uint32_t d0 = lm * 64 + 16 * (lc0 ^ sws);
    const uint32_t d1 = lm * 64 + 16 * ((lc0 + 1) ^ sws);
    const int g0 = 8 * lc0, g1 = 8 * (lc0 + 1);

    // loads a 64-wide K chunk [k0, k0+64) into stage s as two 32-sub-tiles
    #define LOAD_CHUNK(k0, s) do {                                          \
        uint32_t st_ = sb + (s) * STG_SZ;                                   \
        cpa16(st_ + T_A + d0,          AH + aoff + (k0) + g0);              \
        cpa16(st_ + T_A + d1,          AH + aoff + (k0) + g1);              \
        cpa16(st_ + T_A + SUB_SZ + d0, AH + aoff + (k0) + 32 + g0);         \
        cpa16(st_ + T_A + SUB_SZ + d1, AH + aoff + (k0) + 32 + g1);         \
        cpa16(st_ + T_B + d0,          WH + boff + (k0) + g0);              \
        cpa16(st_ + T_B + d1,          WH + boff + (k0) + g1);              \
        cpa16(st_ + T_B + SUB_SZ + d0, WH + boff + (k0) + 32 + g0);         \
        cpa16(st_ + T_B + SUB_SZ + d1, WH + boff + (k0) + 32 + g1);         \
        asm volatile("cp.async.commit_group;" ::: "memory");                \
    } while (0)

    const int wm = (wid & 3) * 32;
    const int wn = (wid >> 2) * 64;
    const int ar0 = wm + (lane & 15);
    const int aK  = (lane >> 4) & 1;
    const int bK  = (lane >> 3) & 1;
    const int bnh = (lane >> 4) & 1;
    const int br0 = wn + (lane & 7);

    float acc[2][8][4];
    #pragma unroll
    for (int i = 0; i < 2; i++)
        #pragma unroll
        for (int j = 0; j < 8; j++)
            #pragma unroll
            for (int q = 0; q < 4; q++)
                acc[i][j][q] = 0.f;

    LOAD_CHUNK(0, 0);
    LOAD_CHUNK(64, 1);

    for (int c = 0; c < 16; c++) {
        const int s = c % 3;
        if (c < 15) asm volatile("cp.async.wait_group 1;" ::: "memory");
        else        asm volatile("cp.async.wait_group 0;" ::: "memory");
        __syncthreads();
        if (c + 2 < 16) LOAD_CHUNK((c + 2) * 64, (c + 2) % 3);

        const uint32_t st = sb + s * STG_SZ;
        #pragma unroll
        for (int kk = 0; kk < 4; kk++) {
            const uint32_t sub = (kk >> 1) * SUB_SZ;
            const int kkk = kk & 1;
            uint32_t ah[2][4], bh[8][2];
            #pragma unroll
            for (int mt = 0; mt < 2; mt++) {
                const int row = ar0 + mt * 16;
                const uint32_t off = (uint32_t)(row * 64
                                   + 16 * ((kkk * 2 + aK) ^ ((row >> 1) & 3)));
                ldm4(ah[mt][0], ah[mt][1], ah[mt][2], ah[mt][3],
                     st + T_A + sub + off);
            }
            #pragma unroll
            for (int p = 0; p < 4; p++) {
                const int row = br0 + (p * 2 + bnh) * 8;
                const uint32_t off = (uint32_t)(row * 64
                                   + 16 * ((kkk * 2 + bK) ^ ((row >> 1) & 3)));
                ldm4(bh[2*p][0], bh[2*p][1], bh[2*p+1][0], bh[2*p+1][1],
                     st + T_B + sub + off);
            }
            #pragma unroll
            for (int mt = 0; mt < 2; mt++)
                #pragma unroll
                for (int nt = 0; nt < 8; nt++)
                    mma16816(acc[mt][nt], ah[mt], bh[nt]);
        }
    }

    // ---- epilogue: f16 output
    const int r0 = lane >> 2;
    const int cc = (lane & 3) * 2;
    #pragma unroll
    for (int mt = 0; mt < 2; mt++) {
        const int mrow = by * 128 + wm + mt * 16 + r0;
        #pragma unroll
        for (int nt = 0; nt < 8; nt++) {
            const int col = bx * 128 + wn + nt * 8 + cc;
            const float b0 = bias[col], b1 = bias[col + 1];
            *(__half2*)&Ch[(size_t)mrow * Hx + col] =
                __floats2half2_rn(acc[mt][nt][0] + b0, acc[mt][nt][1] + b1);
            *(__half2*)&Ch[(size_t)(mrow + 8) * Hx + col] =
                __floats2half2_rn(acc[mt][nt][2] + b0, acc[mt][nt][3] + b1);
        }
    }
}

// ---------------- fp32 -> f16 conversion (coalesced, MLP=4) ----------------
__global__ __launch_bounds__(256) void conv_k(
    const float* __restrict__ src, __half* __restrict__ hi, int n)
{
    const int n4 = n / 4;
    int base = blockIdx.x * (blockDim.x * 4) + threadIdx.x;
    const float4* sp = (const float4*)src;
    __half2* hp = (__half2*)hi;
    float4 v[4];
    int idx[4];
    #pragma unroll
    for (int j = 0; j < 4; j++) {
        idx[j] = base + j * 256;
        if (idx[j] < n4) v[j] = sp[idx[j]];
    }
    #pragma unroll
    for (int j = 0; j < 4; j++) {
        if (idx[j] < n4) {
            hp[idx[j] * 2]     = __floats2half2_rn(v[j].x, v[j].y);
            hp[idx[j] * 2 + 1] = __floats2half2_rn(v[j].z, v[j].w);
        }
    }
}

// ---------------- chunked minLSTM scan (recompute variant) -----------------
__device__ __forceinline__ void gate_pq(__half f16, __half i16, __half h16,
                                        float& p, float& q)
{
    float ea = __expf(__half2float(f16));
    float eb = __expf(__half2float(i16));
    float hv = __half2float(h16);
    float na = ea * (1.f + eb);
    float nb = eb * (1.f + ea);
    float r = fast_rcp(na + nb);
    p = na * r;
    q = nb * r * hv;
}

__global__ __launch_bounds__(256) void scan_p1(
    const __half* __restrict__ F16, const __half* __restrict__ I16,
    const __half* __restrict__ H16,
    float* __restrict__ chP, float* __restrict__ chQ)
{
    int t = blockIdx.x * blockDim.x + threadIdx.x;
    int h = t & (Hx - 1);
    int bc = t >> 10;
    int c = bc & (CC - 1);
    int b = bc >> 5;
    size_t base = ((size_t)b * Sx + (size_t)c * CT) * Hx + h;
    float accP = 1.f, accQ = 0.f;
    #pragma unroll 4
    for (int s = 0; s < CT; s++) {
        size_t idx = base + (size_t)s * Hx;
        float p, q;
        gate_pq(F16[idx], I16[idx], H16[idx], p, q);
        accQ = fmaf(p, accQ, q);
        accP *= p;
    }
    chP[t] = accP;
    chQ[t] = accQ;
}

// p3: computes its own chunk-start prefix from chP/chQ (bit-identical to the
// former p2 serial order), then applies the scan.
__global__ __launch_bounds__(256) void scan_p3(
    const __half* __restrict__ F16, const __half* __restrict__ I16,
    const __half* __restrict__ H16,
    const float* __restrict__ chP, const float* __restrict__ chQ,
    float* __restrict__ Out, __half* __restrict__ OH,
    int writeOut, int writeAH)
{
    int t = blockIdx.x * blockDim.x + threadIdx.x;
    int h = t & (Hx - 1);
    int bc = t >> 10;
    int c = bc & (CC - 1);
    int b = bc >> 5;

    // chunk-start value: prefix over chunks < c for this (b,h)
    float hp = 0.f;
    for (int c2 = 0; c2 < c; c2++) {
        size_t cidx = ((size_t)b * CC + c2) * Hx + h;
        hp = fmaf(chP[cidx], hp, chQ[cidx]);
    }

    size_t base = ((size_t)b * Sx + (size_t)c * CT) * Hx + h;
    #pragma unroll 4
    for (int s = 0; s < CT; s++) {
        size_t idx = base + (size_t)s * Hx;
        float p, q;
        gate_pq(F16[idx], I16[idx], H16[idx], p, q);
        hp = fmaf(p, hp, q);
        if (writeOut) Out[idx] = hp;
        if (writeAH)  OH[idx] = __float2half_rn(hp);
    }
}

// ---------------- small vec-mat --------------------------------------------
__global__ void vecmat_k(const float* __restrict__ X, int xStride,
                         const float* __restrict__ W, const float* __restrict__ bias,
                         const float* __restrict__ res, int resStride,
                         float* __restrict__ out, int Bn, int N)
{
    int gw = (blockIdx.x * blockDim.x + threadIdx.x) >> 5;
    int lane = threadIdx.x & 31;
    if (gw >= Bn * N) return;
    int b = gw / N, n = gw % N;
    const float* xr = X + (size_t)b * xStride;
    const float* wr = W + (size_t)n * Hx;
    float s = 0.f;
    #pragma unroll
    for (int k = lane * 4; k < Hx; k += 128) {
        float4 xv = *(const float4*)(xr + k);
        float4 wv = *(const float4*)(wr + k);
        s += xv.x * wv.x + xv.y * wv.y + xv.z * wv.z + xv.w * wv.w;
    }
    #pragma unroll
    for (int o = 16; o; o >>= 1) s += __shfl_xor_sync(0xffffffffu, s, o);
    if (lane == 0) {
        float v = s + bias[n];
        if (res) v += res[(size_t)b * resStride + n];
        out[(size_t)b * N + n] = v;
    }
}

// ---------------- attention via projection pullback ------------------------
__global__ __launch_bounds__(256) void ku_k(
    const float* __restrict__ q, const float* __restrict__ inw,
    float* __restrict__ u)
{
    int bn = blockIdx.x;
    int n = bn & (NHx - 1), b = bn >> 3;
    __shared__ float qs[DHx];
    if (threadIdx.x < DHx) qs[threadIdx.x] = q[(size_t)b * Hx + n * DHx + threadIdx.x];
    __syncthreads();
    const float* Wk = inw + ((size_t)Hx + (size_t)n * DHx) * Hx;
    #pragma unroll
    for (int m0 = 0; m0 < Hx; m0 += 256) {
        int m = m0 + threadIdx.x;
        float acc = 0.f;
        #pragma unroll 8
        for (int hd = 0; hd < DHx; hd++)
            acc = fmaf(qs[hd], Wk[(size_t)hd * Hx + m], acc);
        u[(size_t)bn * Hx + m] = acc;
    }
}

__global__ __launch_bounds__(256) void scores2_k(
    const float* __restrict__ X, const float* __restrict__ u,
    float* __restrict__ sc)
{
    int b = blockIdx.x >> 4;
    int jt = blockIdx.x & 15;
    __shared__ float us[NHx][Hx];
    for (int i = threadIdx.x; i < NHx * Hx; i += 256)
        us[i >> 10][i & (Hx - 1)] = u[(size_t)b * NHx * Hx + i];
    __syncthreads();
    int wid = threadIdx.x >> 5, lane = threadIdx.x & 31;
    #pragma unroll
    for (int jj = 0; jj < 8; jj++) {
        int j = jt * 64 + wid * 8 + jj;
        const float4* xr = (const float4*)(X + ((size_t)b * Sx + j) * Hx);
        float acc[NHx] = {0.f, 0.f, 0.f, 0.f, 0.f, 0.f, 0.f, 0.f};
        for (int k = lane; k < Hx / 4; k += 32) {
            float4 xv = xr[k];
            #pragma unroll
            for (int n = 0; n < NHx; n++) {
                float4 uv = *(const float4*)&us[n][k * 4];
                acc[n] += xv.x * uv.x + xv.y * uv.y + xv.z * uv.z + xv.w * uv.w;
            }
        }
        #pragma unroll
        for (int n = 0; n < NHx; n++) {
            float s = acc[n];
            #pragma unroll
            for (int o = 16; o; o >>= 1) s += __shfl_xor_sync(0xffffffffu, s, o);
            if (lane == 0)
                sc[((size_t)(b * NHx + n)) * Sx + j] = s * 0.0883883476483184f;
        }
    }
}

__global__ __launch_bounds__(256) void softmax_k(float* __restrict__ sc)
{
    int row = blockIdx.x;
    float4* p = (float4*)(sc + (size_t)row * Sx);
    int t = threadIdx.x;
    float4 v = p[t];
    __shared__ float sh[8];

    float m = fmaxf(fmaxf(v.x, v.y), fmaxf(v.z, v.w));
    #pragma unroll
    for (int o = 16; o; o >>= 1) m = fmaxf(m, __shfl_xor_sync(0xffffffffu, m, o));
    if ((t & 31) == 0) sh[t >> 5] = m;
    __syncthreads();
    m = sh[0];
    #pragma unroll
    for (int i = 1; i < 8; i++) m = fmaxf(m, sh[i]);

    v.x = __expf(v.x - m); v.y = __expf(v.y - m);
    v.z = __expf(v.z - m); v.w = __expf(v.w - m);
    float sum = v.x + v.y + v.z + v.w;
    #pragma unroll
    for (int o = 16; o; o >>= 1) sum += __shfl_xor_sync(0xffffffffu, sum, o);
    __syncthreads();
    if ((t & 31) == 0) sh[t >> 5] = sum;
    __syncthreads();
    sum = 0.f;
    #pragma unroll
    for (int i = 0; i < 8; i++) sum += sh[i];
    float inv = 1.f / sum;
    v.x *= inv; v.y *= inv; v.z *= inv; v.w *= inv;
    p[t] = v;
}

__global__ __launch_bounds__(128) void wsum_k(
    const float* __restrict__ X, const float* __restrict__ sc,
    float* __restrict__ wp)
{
    int b = blockIdx.x, mt = blockIdx.y, jg = blockIdx.z;
    int m = mt * 128 + threadIdx.x;
    __shared__ float as[NHx][128];
    for (int i = threadIdx.x; i < NHx * 128; i += 128)
        as[i >> 7][i & 127] =
            sc[((size_t)(b * NHx + (i >> 7))) * Sx + jg * 128 + (i & 127)];
    __syncthreads();
    float acc[NHx] = {0.f, 0.f, 0.f, 0.f, 0.f, 0.f, 0.f, 0.f};
    const float* xp = X + ((size_t)b * Sx + jg * 128) * Hx + m;
    #pragma unroll 4
    for (int jj = 0; jj < 128; jj++) {
        float xv = xp[(size_t)jj * Hx];
        #pragma unroll
        for (int n = 0; n < NHx; n++) acc[n] = fmaf(as[n][jj], xv, acc[n]);
    }
    #pragma unroll
    for (int n = 0; n < NHx; n++)
        wp[(((size_t)jg * Bx + b) * NHx + n) * Hx + m] = acc[n];
}

__global__ void wred_k(const float* __restrict__ wp, float* __restrict__ w)
{
    int i = blockIdx.x * blockDim.x + threadIdx.x;
    float s = 0.f;
    #pragma unroll
    for (int jg = 0; jg < JG; jg++)
        s += wp[(size_t)jg * (Bx * NHx * Hx) + i];
    w[i] = s;
}

__global__ void ov_k(const float* __restrict__ w, const float* __restrict__ inw,
                     const float* __restrict__ inb, float* __restrict__ o)
{
    int gw = (blockIdx.x * blockDim.x + threadIdx.x) >> 5;
    int lane = threadIdx.x & 31;
    if (gw >= Bx * Hx) return;
    int hd = gw & (Hx - 1), b = gw >> 10;
    int n = hd >> 7;
    const float4* wr = (const float4*)(w + ((size_t)(b * NHx + n)) * Hx);
    const float4* vr = (const float4*)(inw + ((size_t)(2 * Hx + hd)) * Hx);
    float s = 0.f;
    #pragma unroll
    for (int k = lane; k < Hx / 4; k += 32) {
        float4 a = wr[k], c = vr[k];
        s += a.x * c.x + a.y * c.y + a.z * c.z + a.w * c.w;
    }
    #pragma unroll
    for (int o2 = 16; o2; o2 >>= 1) s += __shfl_xor_sync(0xffffffffu, s, o2);
    if (lane == 0) o[(size_t)b * Hx + hd] = s + inb[2 * Hx + hd];
}

// ---------------- launch orchestration -------------------------------------
extern "C" void kernel_launch(void* const* d_in, const int* in_sizes, int n_in,
                              void* d_out, int out_size)
{
    const float* x    = (const float*)d_in[0];
    const float* Wf   = (const float*)d_in[1];
    const float* bf   = (const float*)d_in[2];
    const float* Wi   = (const float*)d_in[3];
    const float* bi   = (const float*)d_in[4];
    const float* Wh   = (const float*)d_in[5];
    const float* bh   = (const float*)d_in[6];
    const float* inw  = (const float*)d_in[7];
    const float* inb  = (const float*)d_in[8];
    const float* outw = (const float*)d_in[9];
    const float* outb = (const float*)d_in[10];
    const float* fcw  = (const float*)d_in[11];
    const float* fcb  = (const float*)d_in[12];
    float* out = (float*)d_out;

    float *bufA, *bufF, *bufI, *bufH, *chP, *chQ;
    float *scoresP, *qP, *uP, *wpP, *wP, *oP, *lastP;
    __half *WHp, *AHp;
    cudaGetSymbolAddress((void**)&bufA, g_bufA);
    cudaGetSymbolAddress((void**)&bufF, g_bufF);
    cudaGetSymbolAddress((void**)&bufI, g_bufI);
    cudaGetSymbolAddress((void**)&bufH, g_bufH);
    cudaGetSymbolAddress((void**)&chP, g_chP);
    cudaGetSymbolAddress((void**)&chQ, g_chQ);
    cudaGetSymbolAddress((void**)&scoresP, g_scores);
    cudaGetSymbolAddress((void**)&qP, g_q);
    cudaGetSymbolAddress((void**)&uP, g_u);
    cudaGetSymbolAddress((void**)&wpP, g_wp);
    cudaGetSymbolAddress((void**)&wP, g_w);
    cudaGetSymbolAddress((void**)&oP, g_o);
    cudaGetSymbolAddress((void**)&lastP, g_last);
    cudaGetSymbolAddress((void**)&WHp, g_WH);
    cudaGetSymbolAddress((void**)&AHp, g_AH);

    __half* F16 = (__half*)bufF;
    __half* I16 = (__half*)bufI;
    __half* H16 = (__half*)bufH;

    static int smemSet = 0;
    if (!smemSet) {
        cudaFuncSetAttribute(hgemm_fused_k,
                             cudaFuncAttributeMaxDynamicSharedMemorySize, SMEMB);
        smemSet = 1;
    }

    // ---- conversions: weights + layer-0 activations (fp16)
    conv_k<<<NWF / 16 / 256, 256>>>(Wf, WHp,           NWF);
    conv_k<<<NWF / 16 / 256, 256>>>(Wi, WHp + NWF,     NWF);
    conv_k<<<NWF / 16 / 256, 256>>>(Wh, WHp + 2 * NWF, NWF);
    conv_k<<<(Mx * Hx) / 16 / 256, 256>>>(x, AHp, Mx * Hx);

    dim3 gl(24, 128);
    const int scanT = Bx * CC * Hx;

    for (int l = 0; l < Lx; l++) {
        size_t wo = (size_t)l * Hx * Hx;
        GemmArgs ga;
        ga.WH[0] = WHp + wo;
        ga.WH[1] = WHp + NWF + wo;
        ga.WH[2] = WHp + 2 * NWF + wo;
        ga.bias[0] = bf + (size_t)l * Hx;
        ga.bias[1] = bi + (size_t)l * Hx;
        ga.bias[2] = bh + (size_t)l * Hx;
        ga.C[0] = F16; ga.C[1] = I16; ga.C[2] = H16;
        hgemm_fused_k<<<gl, 256, SMEMB>>>(AHp, ga);
        scan_p1<<<scanT / 256, 256>>>(F16, I16, H16, chP, chQ);
        scan_p3<<<scanT / 256, 256>>>(F16, I16, H16, chP, chQ, bufA, AHp,
                                      (l == Lx - 1) ? 1 : 0,
                                      (l == Lx - 1) ? 0 : 1);
    }

    // ---- attention on last query row via pullback (exact fp32)
    vecmat_k<<<(Bx * Hx * 32 + 255) / 256, 256>>>(
        bufA + (size_t)(Sx - 1) * Hx, Sx * Hx, inw, inb, nullptr, 0, qP, Bx, Hx);
    ku_k<<<Bx * NHx, 256>>>(qP, inw, uP);
    scores2_k<<<Bx * 16, 256>>>(bufA, uP, scoresP);
    softmax_k<<<Bx * NHx, 256>>>(scoresP);
    wsum_k<<<dim3(Bx, 8, JG), 128>>>(bufA, scoresP, wpP);
    wred_k<<<(Bx * NHx * Hx) / 256, 256>>>(wpP, wP);
    ov_k<<<(Bx * Hx * 32 + 255) / 256, 256>>>(wP, inw, inb, oP);

    // ---- out-proj + residual (last token), then fc head
    vecmat_k<<<(Bx * Hx * 32 + 255) / 256, 256>>>(
        oP, Hx, outw, outb, bufA + (size_t)(Sx - 1) * Hx, Sx * Hx, lastP, Bx, Hx);
    vecmat_k<<<(Bx * Ox * 32 + 255) / 256, 256>>>(
        lastP, Hx, fcw, fcb, nullptr, 0, out, Bx, Ox);
}

// round 16
// speedup vs baseline: 1.1046x; 1.1046x over previous
#include <cuda_runtime.h>
#include <cuda_fp16.h>
#include <math.h>
#include <stdint.h>

// Problem constants
#define Bx  16
#define Sx  1024
#define Hx  1024
#define Ox  256
#define Lx  4
#define NHx 8
#define DHx 128
#define Mx  (Bx*Sx)   // 16384 rows
#define CT  32        // scan chunk length
#define CC  (Sx/CT)   // 32 chunks
#define JG  8         // wsum j-split

typedef unsigned long long u64;

// ---------------- scratch (device globals: no allocation allowed) ----------
__device__ float g_bufA[(size_t)Mx * Hx];   // last-layer fp32 activations
__device__ float g_bufF[(size_t)Mx * Hx];   // f16 gate-f preact (as half)
__device__ float g_bufI[(size_t)Mx * Hx];   // f16 gate-i preact (as half)
__device__ float g_bufH[(size_t)Mx * Hx];   // f16 h~ preact (as half)
__device__ float g_chP[Bx * Hx * CC];
__device__ float g_chQ[Bx * Hx * CC];
__device__ float g_scores[Bx * NHx * Sx];
__device__ float g_q[Bx * Hx];
__device__ float g_u[Bx * NHx * Hx];
__device__ float g_wp[JG * Bx * NHx * Hx];
__device__ float g_w[Bx * NHx * Hx];
__device__ float g_o[Bx * Hx];
__device__ float g_last[Bx * Hx];

// fp16 buffers
#define NWF 4194304
#define NWTOT (3*NWF)
__device__ __half g_WH[NWTOT];
__device__ __half g_AH[(size_t)Mx * Hx];

// ======================= helpers ===========================================
__device__ __forceinline__ uint32_t smem_u32(const void* p) {
    uint32_t a;
    asm("{ .reg .u64 t; cvta.to.shared.u64 t, %1; cvt.u32.u64 %0, t; }"
        : "=r"(a) : "l"(p));
    return a;
}
__device__ __forceinline__ void cpa16(uint32_t dst, const void* src) {
    asm volatile("cp.async.cg.shared.global [%0], [%1], 16;" :: "r"(dst), "l"(src));
}
__device__ __forceinline__ void ldm4(uint32_t& r0, uint32_t& r1,
                                     uint32_t& r2, uint32_t& r3, uint32_t a) {
    asm volatile("ldmatrix.sync.aligned.m8n8.x4.shared.b16 {%0,%1,%2,%3}, [%4];"
        : "=r"(r0), "=r"(r1), "=r"(r2), "=r"(r3) : "r"(a));
}
__device__ __forceinline__ void mma16816(float* d, const uint32_t* a, const uint32_t* b) {
    asm volatile("mma.sync.aligned.m16n8k16.row.col.f32.f16.f16.f32 "
        "{%0,%1,%2,%3}, {%4,%5,%6,%7}, {%8,%9}, {%0,%1,%2,%3};"
        : "+f"(d[0]), "+f"(d[1]), "+f"(d[2]), "+f"(d[3])
        : "r"(a[0]), "r"(a[1]), "r"(a[2]), "r"(a[3]), "r"(b[0]), "r"(b[1]));
}
__device__ __forceinline__ float fast_rcp(float x) {
    float r; asm("rcp.approx.f32 %0, %1;" : "=f"(r) : "f"(x)); return r;
}

// ======================= fused multi-output pure-fp16 HGEMM ================
// R14 config: CTA tile 128x128, 256 threads, K-chunk 32, 4-stage cp.async,
// 64 KB smem (2 CTAs/SM). region = blockIdx.x >> 3. All outputs f16.
struct GemmArgs {
    const __half* WH[3];
    const float*  bias[3];
    __half*       C[3];
};

#define STG_SZ 16384
#define T_A 0
#define T_B 8192
#define NSTG 4
#define SMEMB (NSTG * STG_SZ)   // 64 KB

__global__ __launch_bounds__(256) void hgemm_fused_k(
    const __half* __restrict__ AH, GemmArgs ga)
{
    extern __shared__ __align__(1024) char smem[];
    const uint32_t sb = smem_u32(smem);
    const int tid = threadIdx.x;
    const int wid = tid >> 5, lane = tid & 31;
    const int region = blockIdx.x >> 3;
    const int bx = blockIdx.x & 7;
    const int by = blockIdx.y;

    const __half* WH = ga.WH[region];
    const float*  bias = ga.bias[region];
    __half*       Ch = ga.C[region];

    const int lm  = tid >> 1;
    const int lc0 = (tid & 1) * 2;
    const size_t aoff = (size_t)(by * 128 + lm) * Hx;
    const size_t boff = (size_t)(bx * 128 + lm) * Hx;
    const int sws = (lm >> 1) & 3;
    const uint32_t d0 = lm * 64 + 16 * (lc0 ^ sws);
    const uint32_t d1 = lm * 64 + 16 * ((lc0 + 1) ^ sws);
    const int g0 = 8 * lc0, g1 = 8 * (lc0 + 1);

    #define LOAD_CHUNK(k0, s) do {                                          \
        uint32_t st_ = sb + (s) * STG_SZ;                                   \
        cpa16(st_ + T_A + d0, AH + aoff + (k0) + g0);                       \
        cpa16(st_ + T_A + d1, AH + aoff + (k0) + g1);                       \
        cpa16(st_ + T_B + d0, WH + boff + (k0) + g0);                       \
        cpa16(st_ + T_B + d1, WH + boff + (k0) + g1);                       \
        asm volatile("cp.async.commit_group;" ::: "memory");                \
    } while (0)

    const int wm = (wid & 3) * 32;
    const int wn = (wid >> 2) * 64;
    const int ar0 = wm + (lane & 15);
    const int aK  = (lane >> 4) & 1;
    const int bK  = (lane >> 3) & 1;
    const int bnh = (lane >> 4) & 1;
    const int br0 = wn + (lane & 7);

    float acc[2][8][4];
    #pragma unroll
    for (int i = 0; i < 2; i++)
        #pragma unroll
        for (int j = 0; j < 8; j++)
            #pragma unroll
            for (int q = 0; q < 4; q++)
                acc[i][j][q] = 0.f;

    LOAD_CHUNK(0, 0);
    LOAD_CHUNK(32, 1);
    LOAD_CHUNK(64, 2);

    for (int c = 0; c < 32; c++) {
        const int s = c & (NSTG - 1);
        if (c < 30)       asm volatile("cp.async.wait_group 2;" ::: "memory");
        else if (c == 30) asm volatile("cp.async.wait_group 1;" ::: "memory");
        else              asm volatile("cp.async.wait_group 0;" ::: "memory");
        __syncthreads();
        if (c + 3 < 32) LOAD_CHUNK((c + 3) * 32, (c + 3) & (NSTG - 1));

        const uint32_t st = sb + s * STG_SZ;
        #pragma unroll
        for (int kk = 0; kk < 2; kk++) {
            uint32_t ah[2][4], bh[8][2];
            #pragma unroll
            for (int mt = 0; mt < 2; mt++) {
                const int row = ar0 + mt * 16;
                const uint32_t off = (uint32_t)(row * 64
                                   + 16 * ((kk * 2 + aK) ^ ((row >> 1) & 3)));
                ldm4(ah[mt][0], ah[mt][1], ah[mt][2], ah[mt][3], st + T_A + off);
            }
            #pragma unroll
            for (int p = 0; p < 4; p++) {
                const int row = br0 + (p * 2 + bnh) * 8;
                const uint32_t off = (uint32_t)(row * 64
                                   + 16 * ((kk * 2 + bK) ^ ((row >> 1) & 3)));
                ldm4(bh[2*p][0], bh[2*p][1], bh[2*p+1][0], bh[2*p+1][1], st + T_B + off);
            }
            #pragma unroll
            for (int mt = 0; mt < 2; mt++)
                #pragma unroll
                for (int nt = 0; nt < 8; nt++)
                    mma16816(acc[mt][nt], ah[mt], bh[nt]);
        }
    }

    // ---- epilogue: f16 output
    const int r0 = lane >> 2;
    const int cc = (lane & 3) * 2;
    #pragma unroll
    for (int mt = 0; mt < 2; mt++) {
        const int mrow = by * 128 + wm + mt * 16 + r0;
        #pragma unroll
        for (int nt = 0; nt < 8; nt++) {
            const int col = bx * 128 + wn + nt * 8 + cc;
            const float b0 = bias[col], b1 = bias[col + 1];
            *(__half2*)&Ch[(size_t)mrow * Hx + col] =
                __floats2half2_rn(acc[mt][nt][0] + b0, acc[mt][nt][1] + b1);
            *(__half2*)&Ch[(size_t)(mrow + 8) * Hx + col] =
                __floats2half2_rn(acc[mt][nt][2] + b0, acc[mt][nt][3] + b1);
        }
    }
}

// ---------------- fp32 -> f16 conversion (coalesced, MLP=4) ----------------
__global__ __launch_bounds__(256) void conv_k(
    const float* __restrict__ src, __half* __restrict__ hi, int n)
{
    const int n4 = n / 4;
    int base = blockIdx.x * (blockDim.x * 4) + threadIdx.x;
    const float4* sp = (const float4*)src;
    __half2* hp = (__half2*)hi;
    float4 v[4];
    int idx[4];
    #pragma unroll
    for (int j = 0; j < 4; j++) {
        idx[j] = base + j * 256;
        if (idx[j] < n4) v[j] = sp[idx[j]];
    }
    #pragma unroll
    for (int j = 0; j < 4; j++) {
        if (idx[j] < n4) {
            hp[idx[j] * 2]     = __floats2half2_rn(v[j].x, v[j].y);
            hp[idx[j] * 2 + 1] = __floats2half2_rn(v[j].z, v[j].w);
        }
    }
}

// ---------------- chunked minLSTM scan (recompute, 2-pass) -----------------
__device__ __forceinline__ void gate_pq(__half f16, __half i16, __half h16,
                                        float& p, float& q)
{
    float ea = __expf(__half2float(f16));
    float eb = __expf(__half2float(i16));
    float hv = __half2float(h16);
    float na = ea * (1.f + eb);
    float nb = eb * (1.f + ea);
    float r = fast_rcp(na + nb);
    p = na * r;
    q = nb * r * hv;
}

__global__ __launch_bounds__(256) void scan_p1(
    const __half* __restrict__ F16, const __half* __restrict__ I16,
    const __half* __restrict__ H16,
    float* __restrict__ chP, float* __restrict__ chQ)
{
    int t = blockIdx.x * blockDim.x + threadIdx.x;
    int h = t & (Hx - 1);
    int bc = t >> 10;
    int c = bc & (CC - 1);
    int b = bc >> 5;
    size_t base = ((size_t)b * Sx + (size_t)c * CT) * Hx + h;
    float accP = 1.f, accQ = 0.f;
    #pragma unroll 4
    for (int s = 0; s < CT; s++) {
        size_t idx = base + (size_t)s * Hx;
        float p, q;
        gate_pq(F16[idx], I16[idx], H16[idx], p, q);
        accQ = fmaf(p, accQ, q);
        accP *= p;
    }
    chP[t] = accP;
    chQ[t] = accQ;
}

// p3: computes its own chunk-start prefix from chP/chQ (bit-identical serial
// order), then applies the scan.
__global__ __launch_bounds__(256) void scan_p3(
    const __half* __restrict__ F16, const __half* __restrict__ I16,
    const __half* __restrict__ H16,
    const float* __restrict__ chP, const float* __restrict__ chQ,
    float* __restrict__ Out, __half* __restrict__ OH,
    int writeOut, int writeAH)
{
    int t = blockIdx.x * blockDim.x + threadIdx.x;
    int h = t & (Hx - 1);
    int bc = t >> 10;
    int c = bc & (CC - 1);
    int b = bc >> 5;

    float hp = 0.f;
    for (int c2 = 0; c2 < c; c2++) {
        size_t cidx = ((size_t)b * CC + c2) * Hx + h;
        hp = fmaf(chP[cidx], hp, chQ[cidx]);
    }

    size_t base = ((size_t)b * Sx + (size_t)c * CT) * Hx + h;
    #pragma unroll 4
    for (int s = 0; s < CT; s++) {
        size_t idx = base + (size_t)s * Hx;
        float p, q;
        gate_pq(F16[idx], I16[idx], H16[idx], p, q);
        hp = fmaf(p, hp, q);
        if (writeOut) Out[idx] = hp;
        if (writeAH)  OH[idx] = __float2half_rn(hp);
    }
}

// ---------------- small vec-mat --------------------------------------------
__global__ void vecmat_k(const float* __restrict__ X, int xStride,
                         const float* __restrict__ W, const float* __restrict__ bias,
                         const float* __restrict__ res, int resStride,
                         float* __restrict__ out, int Bn, int N)
{
    int gw = (blockIdx.x * blockDim.x + threadIdx.x) >> 5;
    int lane = threadIdx.x & 31;
    if (gw >= Bn * N) return;
    int b = gw / N, n = gw % N;
    const float* xr = X + (size_t)b * xStride;
    const float* wr = W + (size_t)n * Hx;
    float s = 0.f;
    #pragma unroll
    for (int k = lane * 4; k < Hx; k += 128) {
        float4 xv = *(const float4*)(xr + k);
        float4 wv = *(const float4*)(wr + k);
        s += xv.x * wv.x + xv.y * wv.y + xv.z * wv.z + xv.w * wv.w;
    }
    #pragma unroll
    for (int o = 16; o; o >>= 1) s += __shfl_xor_sync(0xffffffffu, s, o);
    if (lane == 0) {
        float v = s + bias[n];
        if (res) v += res[(size_t)b * resStride + n];
        out[(size_t)b * N + n] = v;
    }
}

// ---------------- attention via projection pullback ------------------------
__global__ __launch_bounds__(256) void ku_k(
    const float* __restrict__ q, const float* __restrict__ inw,
    float* __restrict__ u)
{
    int bn = blockIdx.x;
    int n = bn & (NHx - 1), b = bn >> 3;
    __shared__ float qs[DHx];
    if (threadIdx.x < DHx) qs[threadIdx.x] = q[(size_t)b * Hx + n * DHx + threadIdx.x];
    __syncthreads();
    const float* Wk = inw + ((size_t)Hx + (size_t)n * DHx) * Hx;
    #pragma unroll
    for (int m0 = 0; m0 < Hx; m0 += 256) {
        int m = m0 + threadIdx.x;
        float acc = 0.f;
        #pragma unroll 8
        for (int hd = 0; hd < DHx; hd++)
            acc = fmaf(qs[hd], Wk[(size_t)hd * Hx + m], acc);
        u[(size_t)bn * Hx + m] = acc;
    }
}

__global__ __launch_bounds__(256) void scores2_k(
    const float* __restrict__ X, const float* __restrict__ u,
    float* __restrict__ sc)
{
    int b = blockIdx.x >> 4;
    int jt = blockIdx.x & 15;
    __shared__ float us[NHx][Hx];
    for (int i = threadIdx.x; i < NHx * Hx; i += 256)
        us[i >> 10][i & (Hx - 1)] = u[(size_t)b * NHx * Hx + i];
    __syncthreads();
    int wid = threadIdx.x >> 5, lane = threadIdx.x & 31;
    #pragma unroll
    for (int jj = 0; jj < 8; jj++) {
        int j = jt * 64 + wid * 8 + jj;
        const float4* xr = (const float4*)(X + ((size_t)b * Sx + j) * Hx);
        float acc[NHx] = {0.f, 0.f, 0.f, 0.f, 0.f, 0.f, 0.f, 0.f};
        for (int k = lane; k < Hx / 4; k += 32) {
            float4 xv = xr[k];
            #pragma unroll
            for (int n = 0; n < NHx; n++) {
                float4 uv = *(const float4*)&us[n][k * 4];
                acc[n] += xv.x * uv.x + xv.y * uv.y + xv.z * uv.z + xv.w * uv.w;
            }
        }
        #pragma unroll
        for (int n = 0; n < NHx; n++) {
            float s = acc[n];
            #pragma unroll
            for (int o = 16; o; o >>= 1) s += __shfl_xor_sync(0xffffffffu, s, o);
            if (lane == 0)
                sc[((size_t)(b * NHx + n)) * Sx + j] = s * 0.0883883476483184f;
        }
    }
}

__global__ __launch_bounds__(256) void softmax_k(float* __restrict__ sc)
{
    int row = blockIdx.x;
    float4* p = (float4*)(sc + (size_t)row * Sx);
    int t = threadIdx.x;
    float4 v = p[t];
    __shared__ float sh[8];

    float m = fmaxf(fmaxf(v.x, v.y), fmaxf(v.z, v.w));
    #pragma unroll
    for (int o = 16; o; o >>= 1) m = fmaxf(m, __shfl_xor_sync(0xffffffffu, m, o));
    if ((t & 31) == 0) sh[t >> 5] = m;
    __syncthreads();
    m = sh[0];
    #pragma unroll
    for (int i = 1; i < 8; i++) m = fmaxf(m, sh[i]);

    v.x = __expf(v.x - m); v.y = __expf(v.y - m);
    v.z = __expf(v.z - m); v.w = __expf(v.w - m);
    float sum = v.x + v.y + v.z + v.w;
    #pragma unroll
    for (int o = 16; o; o >>= 1) sum += __shfl_xor_sync(0xffffffffu, sum, o);
    __syncthreads();
    if ((t & 31) == 0) sh[t >> 5] = sum;
    __syncthreads();
    sum = 0.f;
    #pragma unroll
    for (int i = 0; i < 8; i++) sum += sh[i];
    float inv = 1.f / sum;
    v.x *= inv; v.y *= inv; v.z *= inv; v.w *= inv;
    p[t] = v;
}

__global__ __launch_bounds__(128) void wsum_k(
    const float* __restrict__ X, const float* __restrict__ sc,
    float* __restrict__ wp)
{
    int b = blockIdx.x, mt = blockIdx.y, jg = blockIdx.z;
    int m = mt * 128 + threadIdx.x;
    __shared__ float as[NHx][128];
    for (int i = threadIdx.x; i < NHx * 128; i += 128)
        as[i >> 7][i & 127] =
            sc[((size_t)(b * NHx + (i >> 7))) * Sx + jg * 128 + (i & 127)];
    __syncthreads();
    float acc[NHx] = {0.f, 0.f, 0.f, 0.f, 0.f, 0.f, 0.f, 0.f};
    const float* xp = X + ((size_t)b * Sx + jg * 128) * Hx + m;
    #pragma unroll 4
    for (int jj = 0; jj < 128; jj++) {
        float xv = xp[(size_t)jj * Hx];
        #pragma unroll
        for (int n = 0; n < NHx; n++) acc[n] = fmaf(as[n][jj], xv, acc[n]);
    }
    #pragma unroll
    for (int n = 0; n < NHx; n++)
        wp[(((size_t)jg * Bx + b) * NHx + n) * Hx + m] = acc[n];
}

__global__ void wred_k(const float* __restrict__ wp, float* __restrict__ w)
{
    int i = blockIdx.x * blockDim.x + threadIdx.x;
    float s = 0.f;
    #pragma unroll
    for (int jg = 0; jg < JG; jg++)
        s += wp[(size_t)jg * (Bx * NHx * Hx) + i];
    w[i] = s;
}

__global__ void ov_k(const float* __restrict__ w, const float* __restrict__ inw,
                     const float* __restrict__ inb, float* __restrict__ o)
{
    int gw = (blockIdx.x * blockDim.x + threadIdx.x) >> 5;
    int lane = threadIdx.x & 31;
    if (gw >= Bx * Hx) return;
    int hd = gw & (Hx - 1), b = gw >> 10;
    int n = hd >> 7;
    const float4* wr = (const float4*)(w + ((size_t)(b * NHx + n)) * Hx);
    const float4* vr = (const float4*)(inw + ((size_t)(2 * Hx + hd)) * Hx);
    float s = 0.f;
    #pragma unroll
    for (int k = lane; k < Hx / 4; k += 32) {
        float4 a = wr[k], c = vr[k];
        s += a.x * c.x + a.y * c.y + a.z * c.z + a.w * c.w;
    }
    #pragma unroll
    for (int o2 = 16; o2; o2 >>= 1) s += __shfl_xor_sync(0xffffffffu, s, o2);
    if (lane == 0) o[(size_t)b * Hx + hd] = s + inb[2 * Hx + hd];
}

// ---------------- launch orchestration -------------------------------------
extern "C" void kernel_launch(void* const* d_in, const int* in_sizes, int n_in,
                              void* d_out, int out_size)
{
    const float* x    = (const float*)d_in[0];
    const float* Wf   = (const float*)d_in[1];
    const float* bf   = (const float*)d_in[2];
    const float* Wi   = (const float*)d_in[3];
    const float* bi   = (const float*)d_in[4];
    const float* Wh   = (const float*)d_in[5];
    const float* bh   = (const float*)d_in[6];
    const float* inw  = (const float*)d_in[7];
    const float* inb  = (const float*)d_in[8];
    const float* outw = (const float*)d_in[9];
    const float* outb = (const float*)d_in[10];
    const float* fcw  = (const float*)d_in[11];
    const float* fcb  = (const float*)d_in[12];
    float* out = (float*)d_out;

    float *bufA, *bufF, *bufI, *bufH, *chP, *chQ;
    float *scoresP, *qP, *uP, *wpP, *wP, *oP, *lastP;
    __half *WHp, *AHp;
    cudaGetSymbolAddress((void**)&bufA, g_bufA);
    cudaGetSymbolAddress((void**)&bufF, g_bufF);
    cudaGetSymbolAddress((void**)&bufI, g_bufI);
    cudaGetSymbolAddress((void**)&bufH, g_bufH);
    cudaGetSymbolAddress((void**)&chP, g_chP);
    cudaGetSymbolAddress((void**)&chQ, g_chQ);
    cudaGetSymbolAddress((void**)&scoresP, g_scores);
    cudaGetSymbolAddress((void**)&qP, g_q);
    cudaGetSymbolAddress((void**)&uP, g_u);
    cudaGetSymbolAddress((void**)&wpP, g_wp);
    cudaGetSymbolAddress((void**)&wP, g_w);
    cudaGetSymbolAddress((void**)&oP, g_o);
    cudaGetSymbolAddress((void**)&lastP, g_last);
    cudaGetSymbolAddress((void**)&WHp, g_WH);
    cudaGetSymbolAddress((void**)&AHp, g_AH);

    __half* F16 = (__half*)bufF;
    __half* I16 = (__half*)bufI;
    __half* H16 = (__half*)bufH;

    static int smemSet = 0;
    if (!smemSet) {
        cudaFuncSetAttribute(hgemm_fused_k,
                             cudaFuncAttributeMaxDynamicSharedMemorySize, SMEMB);
        smemSet = 1;
    }

    // ---- conversions: weights + layer-0 activations (fp16)
    conv_k<<<NWF / 16 / 256, 256>>>(Wf, WHp,           NWF);
    conv_k<<<NWF / 16 / 256, 256>>>(Wi, WHp + NWF,     NWF);
    conv_k<<<NWF / 16 / 256, 256>>>(Wh, WHp + 2 * NWF, NWF);
    conv_k<<<(Mx * Hx) / 16 / 256, 256>>>(x, AHp, Mx * Hx);

    dim3 gl(24, 128);
    const int scanT = Bx * CC * Hx;

    for (int l = 0; l < Lx; l++) {
        size_t wo = (size_t)l * Hx * Hx;
        GemmArgs ga;
        ga.WH[0] = WHp + wo;
        ga.WH[1] = WHp + NWF + wo;
        ga.WH[2] = WHp + 2 * NWF + wo;
        ga.bias[0] = bf + (size_t)l * Hx;
        ga.bias[1] = bi + (size_t)l * Hx;
        ga.bias[2] = bh + (size_t)l * Hx;
        ga.C[0] = F16; ga.C[1] = I16; ga.C[2] = H16;
        hgemm_fused_k<<<gl, 256, SMEMB>>>(AHp, ga);
        scan_p1<<<scanT / 256, 256>>>(F16, I16, H16, chP, chQ);
        scan_p3<<<scanT / 256, 256>>>(F16, I16, H16, chP, chQ, bufA, AHp,
                                      (l == Lx - 1) ? 1 : 0,
                                      (l == Lx - 1) ? 0 : 1);
    }

    // ---- attention on last query row via pullback (exact fp32)
    vecmat_k<<<(Bx * Hx * 32 + 255) / 256, 256>>>(
        bufA + (size_t)(Sx - 1) * Hx, Sx * Hx, inw, inb, nullptr, 0, qP, Bx, Hx);
    ku_k<<<Bx * NHx, 256>>>(qP, inw, uP);
    scores2_k<<<Bx * 16, 256>>>(bufA, uP, scoresP);
    softmax_k<<<Bx * NHx, 256>>>(scoresP);
    wsum_k<<<dim3(Bx, 8, JG), 128>>>(bufA, scoresP, wpP);
    wred_k<<<(Bx * NHx * Hx) / 256, 256>>>(wpP, wP);
    ov_k<<<(Bx * Hx * 32 + 255) / 256, 256>>>(wP, inw, inb, oP);

    // ---- out-proj + residual (last token), then fc head
    vecmat_k<<<(Bx * Hx * 32 + 255) / 256, 256>>>(
        oP, Hx, outw, outb, bufA + (size_t)(Sx - 1) * Hx, Sx * Hx, lastP, Bx, Hx);
    vecmat_k<<<(Bx * Ox * 32 + 255) / 256, 256>>>(
        lastP, Hx, fcw, fcb, nullptr, 0, out, Bx, Ox);
}

// round 17
// speedup vs baseline: 1.1448x; 1.0364x over previous
#include <cuda_runtime.h>
#include <cuda_fp16.h>
#include <math.h>
#include <stdint.h>

// Problem constants
#define Bx  16
#define Sx  1024
#define Hx  1024
#define Ox  256
#define Lx  4
#define NHx 8
#define DHx 128
#define Mx  (Bx*Sx)   // 16384 rows
#define CT  32        // scan chunk length
#define CC  (Sx/CT)   // 32 chunks
#define JG  8         // wsum j-split

typedef unsigned long long u64;

// ---------------- scratch (device globals: no allocation allowed) ----------
__device__ float g_bufA[(size_t)Mx * Hx];   // last-layer fp32 activations
__device__ float g_bufF[(size_t)Mx * Hx];   // f16 gate-f preact (as half)
__device__ float g_bufI[(size_t)Mx * Hx];   // f16 gate-i preact (as half)
__device__ float g_bufH[(size_t)Mx * Hx];   // f16 h~ preact (as half)
__device__ float g_chP[Bx * Hx * CC];
__device__ float g_chQ[Bx * Hx * CC];
__device__ float g_scores[Bx * NHx * Sx];
__device__ float g_q[Bx * Hx];
__device__ float g_u[Bx * NHx * Hx];
__device__ float g_wp[JG * Bx * NHx * Hx];
__device__ float g_w[Bx * NHx * Hx];
__device__ float g_o[Bx * Hx];
__device__ float g_last[Bx * Hx];

// fp16 buffers
#define NWF 4194304
#define NWTOT (3*NWF)
__device__ __half g_WH[NWTOT];
__device__ __half g_AH[(size_t)Mx * Hx];

// ======================= helpers ===========================================
__device__ __forceinline__ uint32_t smem_u32(const void* p) {
    uint32_t a;
    asm("{ .reg .u64 t; cvta.to.shared.u64 t, %1; cvt.u32.u64 %0, t; }"
        : "=r"(a) : "l"(p));
    return a;
}
__device__ __forceinline__ void cpa16(uint32_t dst, const void* src) {
    asm volatile("cp.async.cg.shared.global [%0], [%1], 16;" :: "r"(dst), "l"(src));
}
__device__ __forceinline__ void ldm4(uint32_t& r0, uint32_t& r1,
                                     uint32_t& r2, uint32_t& r3, uint32_t a) {
    asm volatile("ldmatrix.sync.aligned.m8n8.x4.shared.b16 {%0,%1,%2,%3}, [%4];"
        : "=r"(r0), "=r"(r1), "=r"(r2), "=r"(r3) : "r"(a));
}
__device__ __forceinline__ void mma16816(float* d, const uint32_t* a, const uint32_t* b) {
    asm volatile("mma.sync.aligned.m16n8k16.row.col.f32.f16.f16.f32 "
        "{%0,%1,%2,%3}, {%4,%5,%6,%7}, {%8,%9}, {%0,%1,%2,%3};"
        : "+f"(d[0]), "+f"(d[1]), "+f"(d[2]), "+f"(d[3])
        : "r"(a[0]), "r"(a[1]), "r"(a[2]), "r"(a[3]), "r"(b[0]), "r"(b[1]));
}
__device__ __forceinline__ float fast_rcp(float x) {
    float r; asm("rcp.approx.f32 %0, %1;" : "=f"(r) : "f"(x)); return r;
}

// ======================= fused multi-output pure-fp16 HGEMM ================
// R14 config: CTA tile 128x128, 256 threads, K-chunk 32, 4-stage cp.async,
// 64 KB smem (2 CTAs/SM). region = blockIdx.x >> 3. All outputs f16.
struct GemmArgs {
    const __half* WH[3];
    const float*  bias[3];
    __half*       C[3];
};

#define STG_SZ 16384
#define T_A 0
#define T_B 8192
#define NSTG 4
#define SMEMB (NSTG * STG_SZ)   // 64 KB

__global__ __launch_bounds__(256) void hgemm_fused_k(
    const __half* __restrict__ AH, GemmArgs ga)
{
    extern __shared__ __align__(1024) char smem[];
    const uint32_t sb = smem_u32(smem);
    const int tid = threadIdx.x;
    const int wid = tid >> 5, lane = tid & 31;
    const int region = blockIdx.x >> 3;
    const int bx = blockIdx.x & 7;
    const int by = blockIdx.y;

    const __half* WH = ga.WH[region];
    const float*  bias = ga.bias[region];
    __half*       Ch = ga.C[region];

    const int lm  = tid >> 1;
    const int lc0 = (tid & 1) * 2;
    const size_t aoff = (size_t)(by * 128 + lm) * Hx;
    const size_t boff = (size_t)(bx * 128 + lm) * Hx;
    const int sws = (lm >> 1) & 3;
    const uint32_t d0 = lm * 64 + 16 * (lc0 ^ sws);
    const uint32_t d1 = lm * 64 + 16 * ((lc0 + 1) ^ sws);
    const int g0 = 8 * lc0, g1 = 8 * (lc0 + 1);

    #define LOAD_CHUNK(k0, s) do {                                          \
        uint32_t st_ = sb + (s) * STG_SZ;                                   \
        cpa16(st_ + T_A + d0, AH + aoff + (k0) + g0);                       \
        cpa16(st_ + T_A + d1, AH + aoff + (k0) + g1);                       \
        cpa16(st_ + T_B + d0, WH + boff + (k0) + g0);                       \
        cpa16(st_ + T_B + d1, WH + boff + (k0) + g1);                       \
        asm volatile("cp.async.commit_group;" ::: "memory");                \
    } while (0)

    const int wm = (wid & 3) * 32;
    const int wn = (wid >> 2) * 64;
    const int ar0 = wm + (lane & 15);
    const int aK  = (lane >> 4) & 1;
    const int bK  = (lane >> 3) & 1;
    const int bnh = (lane >> 4) & 1;
    const int br0 = wn + (lane & 7);

    float acc[2][8][4];
    #pragma unroll
    for (int i = 0; i < 2; i++)
        #pragma unroll
        for (int j = 0; j < 8; j++)
            #pragma unroll
            for (int q = 0; q < 4; q++)
                acc[i][j][q] = 0.f;

    LOAD_CHUNK(0, 0);
    LOAD_CHUNK(32, 1);
    LOAD_CHUNK(64, 2);

    for (int c = 0; c < 32; c++) {
        const int s = c & (NSTG - 1);
        if (c < 30)       asm volatile("cp.async.wait_group 2;" ::: "memory");
        else if (c == 30) asm volatile("cp.async.wait_group 1;" ::: "memory");
        else              asm volatile("cp.async.wait_group 0;" ::: "memory");
        __syncthreads();
        if (c + 3 < 32) LOAD_CHUNK((c + 3) * 32, (c + 3) & (NSTG - 1));

        const uint32_t st = sb + s * STG_SZ;
        #pragma unroll
        for (int kk = 0; kk < 2; kk++) {
            uint32_t ah[2][4], bh[8][2];
            #pragma unroll
            for (int mt = 0; mt < 2; mt++) {
                const int row = ar0 + mt * 16;
                const uint32_t off = (uint32_t)(row * 64
                                   + 16 * ((kk * 2 + aK) ^ ((row >> 1) & 3)));
                ldm4(ah[mt][0], ah[mt][1], ah[mt][2], ah[mt][3], st + T_A + off);
            }
            #pragma unroll
            for (int p = 0; p < 4; p++) {
                const int row = br0 + (p * 2 + bnh) * 8;
                const uint32_t off = (uint32_t)(row * 64
                                   + 16 * ((kk * 2 + bK) ^ ((row >> 1) & 3)));
                ldm4(bh[2*p][0], bh[2*p][1], bh[2*p+1][0], bh[2*p+1][1], st + T_B + off);
            }
            #pragma unroll
            for (int mt = 0; mt < 2; mt++)
                #pragma unroll
                for (int nt = 0; nt < 8; nt++)
                    mma16816(acc[mt][nt], ah[mt], bh[nt]);
        }
    }

    // ---- epilogue: f16 output
    const int r0 = lane >> 2;
    const int cc = (lane & 3) * 2;
    #pragma unroll
    for (int mt = 0; mt < 2; mt++) {
        const int mrow = by * 128 + wm + mt * 16 + r0;
        #pragma unroll
        for (int nt = 0; nt < 8; nt++) {
            const int col = bx * 128 + wn + nt * 8 + cc;
            const float b0 = bias[col], b1 = bias[col + 1];
            *(__half2*)&Ch[(size_t)mrow * Hx + col] =
                __floats2half2_rn(acc[mt][nt][0] + b0, acc[mt][nt][1] + b1);
            *(__half2*)&Ch[(size_t)(mrow + 8) * Hx + col] =
                __floats2half2_rn(acc[mt][nt][2] + b0, acc[mt][nt][3] + b1);
        }
    }
}

// ---------------- fp32 -> f16 conversion (coalesced, MLP=4) ----------------
// 3-region weight variant: blockIdx.y selects source / dest region of NWF elems.
__global__ __launch_bounds__(256) void conv3_k(
    const float* __restrict__ s0, const float* __restrict__ s1,
    const float* __restrict__ s2, __half* __restrict__ hi)
{
    const int r = blockIdx.y;
    const float* src = (r == 0) ? s0 : (r == 1) ? s1 : s2;
    __half* dst = hi + (size_t)r * NWF;
    const int n4 = NWF / 4;
    int base = blockIdx.x * (blockDim.x * 4) + threadIdx.x;
    const float4* sp = (const float4*)src;
    __half2* hp = (__half2*)dst;
    float4 v[4];
    int idx[4];
    #pragma unroll
    for (int j = 0; j < 4; j++) {
        idx[j] = base + j * 256;
        if (idx[j] < n4) v[j] = sp[idx[j]];
    }
    #pragma unroll
    for (int j = 0; j < 4; j++) {
        if (idx[j] < n4) {
            hp[idx[j] * 2]     = __floats2half2_rn(v[j].x, v[j].y);
            hp[idx[j] * 2 + 1] = __floats2half2_rn(v[j].z, v[j].w);
        }
    }
}

__global__ __launch_bounds__(256) void conv_k(
    const float* __restrict__ src, __half* __restrict__ hi, int n)
{
    const int n4 = n / 4;
    int base = blockIdx.x * (blockDim.x * 4) + threadIdx.x;
    const float4* sp = (const float4*)src;
    __half2* hp = (__half2*)hi;
    float4 v[4];
    int idx[4];
    #pragma unroll
    for (int j = 0; j < 4; j++) {
        idx[j] = base + j * 256;
        if (idx[j] < n4) v[j] = sp[idx[j]];
    }
    #pragma unroll
    for (int j = 0; j < 4; j++) {
        if (idx[j] < n4) {
            hp[idx[j] * 2]     = __floats2half2_rn(v[j].x, v[j].y);
            hp[idx[j] * 2 + 1] = __floats2half2_rn(v[j].z, v[j].w);
        }
    }
}

// ---------------- chunked minLSTM scan (recompute, 2-pass, half2) ----------
__device__ __forceinline__ void gate_pq(__half f16, __half i16, __half h16,
                                        float& p, float& q)
{
    float ea = __expf(__half2float(f16));
    float eb = __expf(__half2float(i16));
    float hv = __half2float(h16);
    float na = ea * (1.f + eb);
    float nb = eb * (1.f + ea);
    float r = fast_rcp(na + nb);
    p = na * r;
    q = nb * r * hv;
}

// p1: each thread handles 2 adjacent h (half2 loads), 2 independent chains.
__global__ __launch_bounds__(256) void scan_p1(
    const __half* __restrict__ F16, const __half* __restrict__ I16,
    const __half* __restrict__ H16,
    float* __restrict__ chP, float* __restrict__ chQ)
{
    int t = blockIdx.x * blockDim.x + threadIdx.x;   // < Bx*CC*Hx/2
    int h = (t & (Hx / 2 - 1)) * 2;
    int bc = t >> 9;
    int c = bc & (CC - 1);
    int b = bc >> 5;
    size_t base = ((size_t)b * Sx + (size_t)c * CT) * Hx + h;
    float aP0 = 1.f, aQ0 = 0.f, aP1 = 1.f, aQ1 = 0.f;
    #pragma unroll 4
    for (int s = 0; s < CT; s++) {
        size_t idx = base + (size_t)s * Hx;
        __half2 f2 = *(const __half2*)&F16[idx];
        __half2 i2 = *(const __half2*)&I16[idx];
        __half2 h2 = *(const __half2*)&H16[idx];
        float p0, q0, p1, q1;
        gate_pq(__low2half(f2),  __low2half(i2),  __low2half(h2),  p0, q0);
        gate_pq(__high2half(f2), __high2half(i2), __high2half(h2), p1, q1);
        aQ0 = fmaf(p0, aQ0, q0); aP0 *= p0;
        aQ1 = fmaf(p1, aQ1, q1); aP1 *= p1;
    }
    size_t ci = ((size_t)(b * CC + c)) * Hx + h;
    *(float2*)&chP[ci] = make_float2(aP0, aP1);
    *(float2*)&chQ[ci] = make_float2(aQ0, aQ1);
}

// p3: chunk-start prefix from chP/chQ (bit-identical order), then apply.
__global__ __launch_bounds__(256) void scan_p3(
    const __half* __restrict__ F16, const __half* __restrict__ I16,
    const __half* __restrict__ H16,
    const float* __restrict__ chP, const float* __restrict__ chQ,
    float* __restrict__ Out, __half* __restrict__ OH,
    int writeOut, int writeAH)
{
    int t = blockIdx.x * blockDim.x + threadIdx.x;   // < Bx*CC*Hx/2
    int h = (t & (Hx / 2 - 1)) * 2;
    int bc = t >> 9;
    int c = bc & (CC - 1);
    int b = bc >> 5;

    float hp0 = 0.f, hp1 = 0.f;
    for (int c2 = 0; c2 < c; c2++) {
        size_t cidx = ((size_t)(b * CC + c2)) * Hx + h;
        float2 cp = *(const float2*)&chP[cidx];
        float2 cq = *(const float2*)&chQ[cidx];
        hp0 = fmaf(cp.x, hp0, cq.x);
        hp1 = fmaf(cp.y, hp1, cq.y);
    }

    size_t base = ((size_t)b * Sx + (size_t)c * CT) * Hx + h;
    #pragma unroll 4
    for (int s = 0; s < CT; s++) {
        size_t idx = base + (size_t)s * Hx;
        __half2 f2 = *(const __half2*)&F16[idx];
        __half2 i2 = *(const __half2*)&I16[idx];
        __half2 h2 = *(const __half2*)&H16[idx];
        float p0, q0, p1, q1;
        gate_pq(__low2half(f2),  __low2half(i2),  __low2half(h2),  p0, q0);
        gate_pq(__high2half(f2), __high2half(i2), __high2half(h2), p1, q1);
        hp0 = fmaf(p0, hp0, q0);
        hp1 = fmaf(p1, hp1, q1);
        if (writeOut) *(float2*)&Out[idx] = make_float2(hp0, hp1);
        if (writeAH)  *(__half2*)&OH[idx] = __floats2half2_rn(hp0, hp1);
    }
}

// ---------------- small vec-mat --------------------------------------------
__global__ void vecmat_k(const float* __restrict__ X, int xStride,
                         const float* __restrict__ W, const float* __restrict__ bias,
                         const float* __restrict__ res, int resStride,
                         float* __restrict__ out, int Bn, int N)
{
    int gw = (blockIdx.x * blockDim.x + threadIdx.x) >> 5;
    int lane = threadIdx.x & 31;
    if (gw >= Bn * N) return;
    int b = gw / N, n = gw % N;
    const float* xr = X + (size_t)b * xStride;
    const float* wr = W + (size_t)n * Hx;
    float s = 0.f;
    #pragma unroll
    for (int k = lane * 4; k < Hx; k += 128) {
        float4 xv = *(const float4*)(xr + k);
        float4 wv = *(const float4*)(wr + k);
        s += xv.x * wv.x + xv.y * wv.y + xv.z * wv.z + xv.w * wv.w;
    }
    #pragma unroll
    for (int o = 16; o; o >>= 1) s += __shfl_xor_sync(0xffffffffu, s, o);
    if (lane == 0) {
        float v = s + bias[n];
        if (res) v += res[(size_t)b * resStride + n];
        out[(size_t)b * N + n] = v;
    }
}

// ---------------- attention via projection pullback ------------------------
__global__ __launch_bounds__(256) void ku_k(
    const float* __restrict__ q, const float* __restrict__ inw,
    float* __restrict__ u)
{
    int bn = blockIdx.x;
    int n = bn & (NHx - 1), b = bn >> 3;
    __shared__ float qs[DHx];
    if (threadIdx.x < DHx) qs[threadIdx.x] = q[(size_t)b * Hx + n * DHx + threadIdx.x];
    __syncthreads();
    const float* Wk = inw + ((size_t)Hx + (size_t)n * DHx) * Hx;
    #pragma unroll
    for (int m0 = 0; m0 < Hx; m0 += 256) {
        int m = m0 + threadIdx.x;
        float acc = 0.f;
        #pragma unroll 8
        for (int hd = 0; hd < DHx; hd++)
            acc = fmaf(qs[hd], Wk[(size_t)hd * Hx + m], acc);
        u[(size_t)bn * Hx + m] = acc;
    }
}

__global__ __launch_bounds__(256) void scores2_k(
    const float* __restrict__ X, const float* __restrict__ u,
    float* __restrict__ sc)
{
    int b = blockIdx.x >> 4;
    int jt = blockIdx.x & 15;
    __shared__ float us[NHx][Hx];
    for (int i = threadIdx.x; i < NHx * Hx; i += 256)
        us[i >> 10][i & (Hx - 1)] = u[(size_t)b * NHx * Hx + i];
    __syncthreads();
    int wid = threadIdx.x >> 5, lane = threadIdx.x & 31;
    #pragma unroll
    for (int jj = 0; jj < 8; jj++) {
        int j = jt * 64 + wid * 8 + jj;
        const float4* xr = (const float4*)(X + ((size_t)b * Sx + j) * Hx);
        float acc[NHx] = {0.f, 0.f, 0.f, 0.f, 0.f, 0.f, 0.f, 0.f};
        for (int k = lane; k < Hx / 4; k += 32) {
            float4 xv = xr[k];
            #pragma unroll
            for (int n = 0; n < NHx; n++) {
                float4 uv = *(const float4*)&us[n][k * 4];
                acc[n] += xv.x * uv.x + xv.y * uv.y + xv.z * uv.z + xv.w * uv.w;
            }
        }
        #pragma unroll
        for (int n = 0; n < NHx; n++) {
            float s = acc[n];
            #pragma unroll
            for (int o = 16; o; o >>= 1) s += __shfl_xor_sync(0xffffffffu, s, o);
            if (lane == 0)
                sc[((size_t)(b * NHx + n)) * Sx + j] = s * 0.0883883476483184f;
        }
    }
}

__global__ __launch_bounds__(256) void softmax_k(float* __restrict__ sc)
{
    int row = blockIdx.x;
    float4* p = (float4*)(sc + (size_t)row * Sx);
    int t = threadIdx.x;
    float4 v = p[t];
    __shared__ float sh[8];

    float m = fmaxf(fmaxf(v.x, v.y), fmaxf(v.z, v.w));
    #pragma unroll
    for (int o = 16; o; o >>= 1) m = fmaxf(m, __shfl_xor_sync(0xffffffffu, m, o));
    if ((t & 31) == 0) sh[t >> 5] = m;
    __syncthreads();
    m = sh[0];
    #pragma unroll
    for (int i = 1; i < 8; i++) m = fmaxf(m, sh[i]);

    v.x = __expf(v.x - m); v.y = __expf(v.y - m);
    v.z = __expf(v.z - m); v.w = __expf(v.w - m);
    float sum = v.x + v.y + v.z + v.w;
    #pragma unroll
    for (int o = 16; o; o >>= 1) sum += __shfl_xor_sync(0xffffffffu, sum, o);
    __syncthreads();
    if ((t & 31) == 0) sh[t >> 5] = sum;
    __syncthreads();
    sum = 0.f;
    #pragma unroll
    for (int i = 0; i < 8; i++) sum += sh[i];
    float inv = 1.f / sum;
    v.x *= inv; v.y *= inv; v.z *= inv; v.w *= inv;
    p[t] = v;
}

__global__ __launch_bounds__(128) void wsum_k(
    const float* __restrict__ X, const float* __restrict__ sc,
    float* __restrict__ wp)
{
    int b = blockIdx.x, mt = blockIdx.y, jg = blockIdx.z;
    int m = mt * 128 + threadIdx.x;
    __shared__ float as[NHx][128];
    for (int i = threadIdx.x; i < NHx * 128; i += 128)
        as[i >> 7][i & 127] =
            sc[((size_t)(b * NHx + (i >> 7))) * Sx + jg * 128 + (i & 127)];
    __syncthreads();
    float acc[NHx] = {0.f, 0.f, 0.f, 0.f, 0.f, 0.f, 0.f, 0.f};
    const float* xp = X + ((size_t)b * Sx + jg * 128) * Hx + m;
    #pragma unroll 4
    for (int jj = 0; jj < 128; jj++) {
        float xv = xp[(size_t)jj * Hx];
        #pragma unroll
        for (int n = 0; n < NHx; n++) acc[n] = fmaf(as[n][jj], xv, acc[n]);
    }
    #pragma unroll
    for (int n = 0; n < NHx; n++)
        wp[(((size_t)jg * Bx + b) * NHx + n) * Hx + m] = acc[n];
}

__global__ void wred_k(const float* __restrict__ wp, float* __restrict__ w)
{
    int i = blockIdx.x * blockDim.x + threadIdx.x;
    float s = 0.f;
    #pragma unroll
    for (int jg = 0; jg < JG; jg++)
        s += wp[(size_t)jg * (Bx * NHx * Hx) + i];
    w[i] = s;
}

__global__ void ov_k(const float* __restrict__ w, const float* __restrict__ inw,
                     const float* __restrict__ inb, float* __restrict__ o)
{
    int gw = (blockIdx.x * blockDim.x + threadIdx.x) >> 5;
    int lane = threadIdx.x & 31;
    if (gw >= Bx * Hx) return;
    int hd = gw & (Hx - 1), b = gw >> 10;
    int n = hd >> 7;
    const float4* wr = (const float4*)(w + ((size_t)(b * NHx + n)) * Hx);
    const float4* vr = (const float4*)(inw + ((size_t)(2 * Hx + hd)) * Hx);
    float s = 0.f;
    #pragma unroll
    for (int k = lane; k < Hx / 4; k += 32) {
        float4 a = wr[k], c = vr[k];
        s += a.x * c.x + a.y * c.y + a.z * c.z + a.w * c.w;
    }
    #pragma unroll
    for (int o2 = 16; o2; o2 >>= 1) s += __shfl_xor_sync(0xffffffffu, s, o2);
    if (lane == 0) o[(size_t)b * Hx + hd] = s + inb[2 * Hx + hd];
}

// ---------------- launch orchestration -------------------------------------
extern "C" void kernel_launch(void* const* d_in, const int* in_sizes, int n_in,
                              void* d_out, int out_size)
{
    const float* x    = (const float*)d_in[0];
    const float* Wf   = (const float*)d_in[1];
    const float* bf   = (const float*)d_in[2];
    const float* Wi   = (const float*)d_in[3];
    const float* bi   = (const float*)d_in[4];
    const float* Wh   = (const float*)d_in[5];
    const float* bh   = (const float*)d_in[6];
    const float* inw  = (const float*)d_in[7];
    const float* inb  = (const float*)d_in[8];
    const float* outw = (const float*)d_in[9];
    const float* outb = (const float*)d_in[10];
    const float* fcw  = (const float*)d_in[11];
    const float* fcb  = (const float*)d_in[12];
    float* out = (float*)d_out;

    float *bufA, *bufF, *bufI, *bufH, *chP, *chQ;
    float *scoresP, *qP, *uP, *wpP, *wP, *oP, *lastP;
    __half *WHp, *AHp;
    cudaGetSymbolAddress((void**)&bufA, g_bufA);
    cudaGetSymbolAddress((void**)&bufF, g_bufF);
    cudaGetSymbolAddress((void**)&bufI, g_bufI);
    cudaGetSymbolAddress((void**)&bufH, g_bufH);
    cudaGetSymbolAddress((void**)&chP, g_chP);
    cudaGetSymbolAddress((void**)&chQ, g_chQ);
    cudaGetSymbolAddress((void**)&scoresP, g_scores);
    cudaGetSymbolAddress((void**)&qP, g_q);
    cudaGetSymbolAddress((void**)&uP, g_u);
    cudaGetSymbolAddress((void**)&wpP, g_wp);
    cudaGetSymbolAddress((void**)&wP, g_w);
    cudaGetSymbolAddress((void**)&oP, g_o);
    cudaGetSymbolAddress((void**)&lastP, g_last);
    cudaGetSymbolAddress((void**)&WHp, g_WH);
    cudaGetSymbolAddress((void**)&AHp, g_AH);

    __half* F16 = (__half*)bufF;
    __half* I16 = (__half*)bufI;
    __half* H16 = (__half*)bufH;

    static int smemSet = 0;
    if (!smemSet) {
        cudaFuncSetAttribute(hgemm_fused_k,
                             cudaFuncAttributeMaxDynamicSharedMemorySize, SMEMB);
        smemSet = 1;
    }

    // ---- conversions: weights (one fused launch) + layer-0 activations
    conv3_k<<<dim3(NWF / 16 / 256, 3), 256>>>(Wf, Wi, Wh, WHp);
    conv_k<<<(Mx * Hx) / 16 / 256, 256>>>(x, AHp, Mx * Hx);

    dim3 gl(24, 128);
    const int scanT2 = Bx * CC * Hx / 2;   // 256K threads (2 h per thread)

    for (int l = 0; l < Lx; l++) {
        size_t wo = (size_t)l * Hx * Hx;
        GemmArgs ga;
        ga.WH[0] = WHp + wo;
        ga.WH[1] = WHp + NWF + wo;
        ga.WH[2] = WHp + 2 * NWF + wo;
        ga.bias[0] = bf + (size_t)l * Hx;
        ga.bias[1] = bi + (size_t)l * Hx;
        ga.bias[2] = bh + (size_t)l * Hx;
        ga.C[0] = F16; ga.C[1] = I16; ga.C[2] = H16;
        hgemm_fused_k<<<gl, 256, SMEMB>>>(AHp, ga);
        scan_p1<<<scanT2 / 256, 256>>>(F16, I16, H16, chP, chQ);
        scan_p3<<<scanT2 / 256, 256>>>(F16, I16, H16, chP, chQ, bufA, AHp,
                                       (l == Lx - 1) ? 1 : 0,
                                       (l == Lx - 1) ? 0 : 1);
    }

    // ---- attention on last query row via pullback (exact fp32)
    vecmat_k<<<(Bx * Hx * 32 + 255) / 256, 256>>>(
        bufA + (size_t)(Sx - 1) * Hx, Sx * Hx, inw, inb, nullptr, 0, qP, Bx, Hx);
    ku_k<<<Bx * NHx, 256>>>(qP, inw, uP);
    scores2_k<<<Bx * 16, 256>>>(bufA, uP, scoresP);
    softmax_k<<<Bx * NHx, 256>>>(scoresP);
    wsum_k<<<dim3(Bx, 8, JG), 128>>>(bufA, scoresP, wpP);
    wred_k<<<(Bx * NHx * Hx) / 256, 256>>>(wpP, wP);
    ov_k<<<(Bx * Hx * 32 + 255) / 256, 256>>>(wP, inw, inb, oP);

    // ---- out-proj + residual (last token), then fc head
    vecmat_k<<<(Bx * Hx * 32 + 255) / 256, 256>>>(
        oP, Hx, outw, outb, bufA + (size_t)(Sx - 1) * Hx, Sx * Hx, lastP, Bx, Hx);
    vecmat_k<<<(Bx * Ox * 32 + 255) / 256, 256>>>(
        lastP, Hx, fcw, fcb, nullptr, 0, out, Bx, Ox);
}